// round 2
// baseline (speedup 1.0000x reference)
#include <cuda_runtime.h>
#include <math.h>

// Problem constants
#define B_ 4
#define S_ 2048
#define E_ 1024
#define H_ 16
#define D_ 64
#define L_ 4
#define M_ (B_ * S_)          // 8192 rows
#define ACT_ELEMS (8388608)   // B*S*E

// ---------------------------------------------------------------------------
// Scratch buffers (static device globals: allocation-guard safe)
// ---------------------------------------------------------------------------
__device__ float g_q[ACT_ELEMS];
__device__ float g_k[ACT_ELEMS];
__device__ float g_v[ACT_ELEMS];
__device__ float g_att[ACT_ELEMS];
__device__ float g_o[ACT_ELEMS];
__device__ float g_x[ACT_ELEMS];

// ---------------------------------------------------------------------------
// GEMM core: C[M,N] = A[M,K] @ W[N,K]^T + bias[N]
// 128x128 block tile, BK=8, 256 threads, 8x8 per thread.
// ---------------------------------------------------------------------------
__device__ __forceinline__ void gemm_body(
    const float* __restrict__ A, const float* __restrict__ W,
    const float* __restrict__ bias, float* __restrict__ C,
    int M, int N, int K, int bm, int bn)
{
    __shared__ float As[8][128];
    __shared__ float Bs[8][128];

    const int tid = threadIdx.x;
    const int ty = tid >> 4;          // 0..15
    const int tx = tid & 15;          // 0..15
    const int row0 = ty * 8;
    const int col0 = tx * 8;

    float c[8][8];
#pragma unroll
    for (int i = 0; i < 8; i++)
#pragma unroll
        for (int j = 0; j < 8; j++) c[i][j] = 0.0f;

    const int lrow = tid >> 1;            // 0..127
    const int kof  = (tid & 1) * 4;       // 0 or 4
    const float* Aptr = A + (size_t)(bm + lrow) * K + kof;
    const float* Wptr = W + (size_t)(bn + lrow) * K + kof;

    for (int k0 = 0; k0 < K; k0 += 8) {
        float4 av = *(const float4*)(Aptr + k0);
        float4 wv = *(const float4*)(Wptr + k0);
        As[kof + 0][lrow] = av.x; As[kof + 1][lrow] = av.y;
        As[kof + 2][lrow] = av.z; As[kof + 3][lrow] = av.w;
        Bs[kof + 0][lrow] = wv.x; Bs[kof + 1][lrow] = wv.y;
        Bs[kof + 2][lrow] = wv.z; Bs[kof + 3][lrow] = wv.w;
        __syncthreads();

#pragma unroll
        for (int kk = 0; kk < 8; kk++) {
            float a[8], b[8];
            *(float4*)(a)     = *(const float4*)&As[kk][row0];
            *(float4*)(a + 4) = *(const float4*)&As[kk][row0 + 4];
            *(float4*)(b)     = *(const float4*)&Bs[kk][col0];
            *(float4*)(b + 4) = *(const float4*)&Bs[kk][col0 + 4];
#pragma unroll
            for (int i = 0; i < 8; i++)
#pragma unroll
                for (int j = 0; j < 8; j++)
                    c[i][j] = fmaf(a[i], b[j], c[i][j]);
        }
        __syncthreads();
    }

    float bvals[8];
#pragma unroll
    for (int j = 0; j < 8; j++) bvals[j] = bias[bn + col0 + j];

#pragma unroll
    for (int i = 0; i < 8; i++) {
        float* crow = C + (size_t)(bm + row0 + i) * N + bn + col0;
        float4 lo, hi;
        lo.x = c[i][0] + bvals[0]; lo.y = c[i][1] + bvals[1];
        lo.z = c[i][2] + bvals[2]; lo.w = c[i][3] + bvals[3];
        hi.x = c[i][4] + bvals[4]; hi.y = c[i][5] + bvals[5];
        hi.z = c[i][6] + bvals[6]; hi.w = c[i][7] + bvals[7];
        *(float4*)(crow)     = lo;
        *(float4*)(crow + 4) = hi;
    }
}

// Fused Q/K/V projection: blockIdx.z in {0,1,2} selects W/b/output.
__global__ __launch_bounds__(256) void gemm_qkv_kernel(
    const float* __restrict__ A,
    const float* __restrict__ Wq, const float* __restrict__ Wk,
    const float* __restrict__ Wv,
    const float* __restrict__ bq, const float* __restrict__ bk,
    const float* __restrict__ bv,
    float* __restrict__ Qo, float* __restrict__ Ko, float* __restrict__ Vo)
{
    const float* W; const float* bias; float* C;
    if (blockIdx.z == 0)      { W = Wq; bias = bq; C = Qo; }
    else if (blockIdx.z == 1) { W = Wk; bias = bk; C = Ko; }
    else                      { W = Wv; bias = bv; C = Vo; }
    gemm_body(A, W, bias, C, M_, E_, E_, blockIdx.y * 128, blockIdx.x * 128);
}

__global__ __launch_bounds__(256) void gemm_bias_kernel(
    const float* __restrict__ A, const float* __restrict__ W,
    const float* __restrict__ bias, float* __restrict__ C)
{
    gemm_body(A, W, bias, C, M_, E_, E_, blockIdx.y * 128, blockIdx.x * 128);
}

// ---------------------------------------------------------------------------
// Flash-style attention.
// One block per (query-tile of 64, head, batch). 256 threads as 16x16,
// each thread owns a 4(q) x 4(k or d) fragment.
// Replicates: energy = mask ? -1e-10 : q.k ; softmax(energy / 32)
// All smem tiles padded to 65 floats/row to avoid bank conflicts.
// ---------------------------------------------------------------------------
#define ATT_PAD 65
#define ATT_SMEM_FLOATS (4 * 64 * ATT_PAD)
#define ATT_SMEM_BYTES  (ATT_SMEM_FLOATS * 4)

__global__ __launch_bounds__(256) void attn_kernel(
    const float* __restrict__ Q, const float* __restrict__ K,
    const float* __restrict__ V, const int* __restrict__ mask,
    float* __restrict__ O)
{
    extern __shared__ float sm[];
    float* Qs = sm;                       // [64][65]
    float* Ks = Qs + 64 * ATT_PAD;        // [64][65]
    float* Vs = Ks + 64 * ATT_PAD;        // [64][65]
    float* Ps = Vs + 64 * ATT_PAD;        // [64][65]
    __shared__ int mk[64];

    const int qt = blockIdx.x;   // 0..31
    const int h  = blockIdx.y;   // 0..15
    const int b  = blockIdx.z;   // 0..3
    const int tid = threadIdx.x;
    const int ty = tid >> 4;
    const int tx = tid & 15;

    const size_t base = (size_t)b * S_ * E_ + (size_t)h * D_;

    // Load Q tile (64 rows x 64 dims)
    for (int idx = tid; idx < 64 * 16; idx += 256) {
        int r  = idx >> 4;
        int c4 = (idx & 15) * 4;
        float4 qv = *(const float4*)(Q + base + (size_t)(qt * 64 + r) * E_ + c4);
        Qs[r * ATT_PAD + c4 + 0] = qv.x;
        Qs[r * ATT_PAD + c4 + 1] = qv.y;
        Qs[r * ATT_PAD + c4 + 2] = qv.z;
        Qs[r * ATT_PAD + c4 + 3] = qv.w;
    }

    float m[4], l[4], acc[4][4];
#pragma unroll
    for (int i = 0; i < 4; i++) {
        m[i] = -1e30f; l[i] = 0.0f;
#pragma unroll
        for (int j = 0; j < 4; j++) acc[i][j] = 0.0f;
    }

    const float inv_scale = 1.0f / 32.0f;   // 1/sqrt(E), E=1024

    for (int kt = 0; kt < S_ / 64; kt++) {
        __syncthreads();   // protect Ks/Vs (prev compute) and Ps (prev PV reads)

        // Load K and V tiles
        for (int idx = tid; idx < 64 * 16; idx += 256) {
            int r  = idx >> 4;
            int c4 = (idx & 15) * 4;
            float4 kv = *(const float4*)(K + base + (size_t)(kt * 64 + r) * E_ + c4);
            Ks[r * ATT_PAD + c4 + 0] = kv.x;
            Ks[r * ATT_PAD + c4 + 1] = kv.y;
            Ks[r * ATT_PAD + c4 + 2] = kv.z;
            Ks[r * ATT_PAD + c4 + 3] = kv.w;
            float4 vv = *(const float4*)(V + base + (size_t)(kt * 64 + r) * E_ + c4);
            Vs[r * ATT_PAD + c4 + 0] = vv.x;
            Vs[r * ATT_PAD + c4 + 1] = vv.y;
            Vs[r * ATT_PAD + c4 + 2] = vv.z;
            Vs[r * ATT_PAD + c4 + 3] = vv.w;
        }
        if (tid < 64) mk[tid] = mask[(size_t)b * S_ + kt * 64 + tid];
        __syncthreads();

        // S = Q @ K^T fragment (4x4)
        float s[4][4];
#pragma unroll
        for (int i = 0; i < 4; i++)
#pragma unroll
            for (int j = 0; j < 4; j++) s[i][j] = 0.0f;

#pragma unroll 4
        for (int d = 0; d < 64; d++) {
            float a0 = Qs[(ty * 4 + 0) * ATT_PAD + d];
            float a1 = Qs[(ty * 4 + 1) * ATT_PAD + d];
            float a2 = Qs[(ty * 4 + 2) * ATT_PAD + d];
            float a3 = Qs[(ty * 4 + 3) * ATT_PAD + d];
            float b0 = Ks[(tx * 4 + 0) * ATT_PAD + d];
            float b1 = Ks[(tx * 4 + 1) * ATT_PAD + d];
            float b2 = Ks[(tx * 4 + 2) * ATT_PAD + d];
            float b3 = Ks[(tx * 4 + 3) * ATT_PAD + d];
            s[0][0] = fmaf(a0, b0, s[0][0]); s[0][1] = fmaf(a0, b1, s[0][1]);
            s[0][2] = fmaf(a0, b2, s[0][2]); s[0][3] = fmaf(a0, b3, s[0][3]);
            s[1][0] = fmaf(a1, b0, s[1][0]); s[1][1] = fmaf(a1, b1, s[1][1]);
            s[1][2] = fmaf(a1, b2, s[1][2]); s[1][3] = fmaf(a1, b3, s[1][3]);
            s[2][0] = fmaf(a2, b0, s[2][0]); s[2][1] = fmaf(a2, b1, s[2][1]);
            s[2][2] = fmaf(a2, b2, s[2][2]); s[2][3] = fmaf(a2, b3, s[2][3]);
            s[3][0] = fmaf(a3, b0, s[3][0]); s[3][1] = fmaf(a3, b1, s[3][1]);
            s[3][2] = fmaf(a3, b2, s[3][2]); s[3][3] = fmaf(a3, b3, s[3][3]);
        }

        // Mask (replicating the reference: masked energy := -1e-10) then scale
#pragma unroll
        for (int j = 0; j < 4; j++) {
            const int masked = mk[tx * 4 + j];
#pragma unroll
            for (int i = 0; i < 4; i++) {
                float e = masked ? -1e-10f : s[i][j];
                s[i][j] = e * inv_scale;
            }
        }

        // Online softmax (row reductions across the 16 tx lanes, width-16 shfl)
#pragma unroll
        for (int i = 0; i < 4; i++) {
            float tm = fmaxf(fmaxf(s[i][0], s[i][1]), fmaxf(s[i][2], s[i][3]));
#pragma unroll
            for (int off = 8; off > 0; off >>= 1)
                tm = fmaxf(tm, __shfl_xor_sync(0xffffffffu, tm, off, 16));
            float mnew = fmaxf(m[i], tm);

            float tl = 0.0f;
#pragma unroll
            for (int j = 0; j < 4; j++) {
                s[i][j] = expf(s[i][j] - mnew);
                tl += s[i][j];
            }
#pragma unroll
            for (int off = 8; off > 0; off >>= 1)
                tl += __shfl_xor_sync(0xffffffffu, tl, off, 16);

            float fac = expf(m[i] - mnew);
            l[i] = l[i] * fac + tl;
            m[i] = mnew;
#pragma unroll
            for (int j = 0; j < 4; j++) acc[i][j] *= fac;
        }

        // Write P fragment, then acc += P @ V
#pragma unroll
        for (int i = 0; i < 4; i++)
#pragma unroll
            for (int j = 0; j < 4; j++)
                Ps[(ty * 4 + i) * ATT_PAD + tx * 4 + j] = s[i][j];
        __syncthreads();

#pragma unroll 4
        for (int kk = 0; kk < 64; kk++) {
            float p0 = Ps[(ty * 4 + 0) * ATT_PAD + kk];
            float p1 = Ps[(ty * 4 + 1) * ATT_PAD + kk];
            float p2 = Ps[(ty * 4 + 2) * ATT_PAD + kk];
            float p3 = Ps[(ty * 4 + 3) * ATT_PAD + kk];
            float v0 = Vs[kk * ATT_PAD + tx * 4 + 0];
            float v1 = Vs[kk * ATT_PAD + tx * 4 + 1];
            float v2 = Vs[kk * ATT_PAD + tx * 4 + 2];
            float v3 = Vs[kk * ATT_PAD + tx * 4 + 3];
            acc[0][0] = fmaf(p0, v0, acc[0][0]); acc[0][1] = fmaf(p0, v1, acc[0][1]);
            acc[0][2] = fmaf(p0, v2, acc[0][2]); acc[0][3] = fmaf(p0, v3, acc[0][3]);
            acc[1][0] = fmaf(p1, v0, acc[1][0]); acc[1][1] = fmaf(p1, v1, acc[1][1]);
            acc[1][2] = fmaf(p1, v2, acc[1][2]); acc[1][3] = fmaf(p1, v3, acc[1][3]);
            acc[2][0] = fmaf(p2, v0, acc[2][0]); acc[2][1] = fmaf(p2, v1, acc[2][1]);
            acc[2][2] = fmaf(p2, v2, acc[2][2]); acc[2][3] = fmaf(p2, v3, acc[2][3]);
            acc[3][0] = fmaf(p3, v0, acc[3][0]); acc[3][1] = fmaf(p3, v1, acc[3][1]);
            acc[3][2] = fmaf(p3, v2, acc[3][2]); acc[3][3] = fmaf(p3, v3, acc[3][3]);
        }
    }

    // Final normalize + write
#pragma unroll
    for (int i = 0; i < 4; i++) {
        float invl = 1.0f / l[i];
        int qrow = qt * 64 + ty * 4 + i;
        float* op = O + ((size_t)b * S_ + qrow) * E_ + (size_t)h * D_ + tx * 4;
#pragma unroll
        for (int j = 0; j < 4; j++) op[j] = acc[i][j] * invl;
    }
}

// ---------------------------------------------------------------------------
// Residual add + LayerNorm. One block per row (1024 cols, 256 threads x 4).
// ---------------------------------------------------------------------------
__global__ __launch_bounds__(256) void resid_ln_kernel(
    const float* __restrict__ o, const float* __restrict__ x,
    const float* __restrict__ gamma, const float* __restrict__ beta,
    float* __restrict__ out)
{
    const int row = blockIdx.x;
    const int tid = threadIdx.x;
    const float* orow = o + (size_t)row * E_;
    const float* xrow = x + (size_t)row * E_;

    float y[4];
    float s = 0.0f, s2 = 0.0f;
#pragma unroll
    for (int t = 0; t < 4; t++) {
        int c = tid + t * 256;
        y[t] = orow[c] + xrow[c];
        s += y[t];
        s2 += y[t] * y[t];
    }

    __shared__ float red[16];
#pragma unroll
    for (int off = 16; off > 0; off >>= 1) {
        s  += __shfl_xor_sync(0xffffffffu, s, off);
        s2 += __shfl_xor_sync(0xffffffffu, s2, off);
    }
    const int warp = tid >> 5, lane = tid & 31;
    if (lane == 0) { red[warp] = s; red[8 + warp] = s2; }
    __syncthreads();

    float ts = 0.0f, ts2 = 0.0f;
#pragma unroll
    for (int w = 0; w < 8; w++) { ts += red[w]; ts2 += red[8 + w]; }

    const float mu  = ts * (1.0f / E_);
    const float var = ts2 * (1.0f / E_) - mu * mu;
    const float inv = rsqrtf(var + 1e-5f);

    float* outrow = out + (size_t)row * E_;
#pragma unroll
    for (int t = 0; t < 4; t++) {
        int c = tid + t * 256;
        outrow[c] = (y[t] - mu) * inv * gamma[c] + beta[c];
    }
}

// ---------------------------------------------------------------------------
// Launch
// ---------------------------------------------------------------------------
extern "C" void kernel_launch(void* const* d_in, const int* in_sizes, int n_in,
                              void* d_out, int out_size)
{
    (void)in_sizes; (void)n_in; (void)out_size;

    const float* value = (const float*)d_in[0];
    const int*   mask  = (const int*)d_in[1];
    const float* Wq = (const float*)d_in[2];  const float* bq = (const float*)d_in[3];
    const float* Wk = (const float*)d_in[4];  const float* bk = (const float*)d_in[5];
    const float* Wv = (const float*)d_in[6];  const float* bv = (const float*)d_in[7];
    const float* Wo = (const float*)d_in[8];  const float* bo = (const float*)d_in[9];
    const float* gamma = (const float*)d_in[10];
    const float* beta  = (const float*)d_in[11];
    float* out = (float*)d_out;

    float *q, *k, *v, *att, *o, *x;
    cudaGetSymbolAddress((void**)&q,   g_q);
    cudaGetSymbolAddress((void**)&k,   g_k);
    cudaGetSymbolAddress((void**)&v,   g_v);
    cudaGetSymbolAddress((void**)&att, g_att);
    cudaGetSymbolAddress((void**)&o,   g_o);
    cudaGetSymbolAddress((void**)&x,   g_x);

    cudaFuncSetAttribute(attn_kernel,
                         cudaFuncAttributeMaxDynamicSharedMemorySize,
                         ATT_SMEM_BYTES);

    dim3 qkvgrid(E_ / 128, M_ / 128, 3);  // (8, 64, 3)
    dim3 ggrid(E_ / 128, M_ / 128);       // (8, 64)
    dim3 agrid(S_ / 64, H_, B_);          // (32, 16, 4)

    const float* xin = value;
    for (int l = 0; l < L_; l++) {
        size_t wof = (size_t)l * E_ * E_;
        size_t bof = (size_t)l * E_;

        gemm_qkv_kernel<<<qkvgrid, 256>>>(xin,
                                          Wq + wof, Wk + wof, Wv + wof,
                                          bq + bof, bk + bof, bv + bof,
                                          q, k, v);

        attn_kernel<<<agrid, 256, ATT_SMEM_BYTES>>>(q, k, v, mask, att);

        gemm_bias_kernel<<<ggrid, 256>>>(att, Wo + wof, bo + bof, o);

        float* dst = (l == L_ - 1) ? out : x;
        resid_ln_kernel<<<M_, 256>>>(o, xin, gamma + bof, beta + bof, dst);
        xin = x;
    }
}

// round 5
// speedup vs baseline: 2.6856x; 2.6856x over previous
#include <cuda_runtime.h>
#include <cuda_bf16.h>
#include <math.h>

// Problem constants
#define B_ 4
#define S_ 2048
#define E_ 1024
#define H_ 16
#define D_ 64
#define L_ 4
#define M_ 8192
#define ACT_ELEMS 8388608     // B*S*E
#define WELEMS 1048576        // E*E
#define GK E_

// ---------------------------------------------------------------------------
// Scratch (static device globals)
// ---------------------------------------------------------------------------
__device__ float g_q[ACT_ELEMS];
__device__ float g_k[ACT_ELEMS];
__device__ float g_v[ACT_ELEMS];
__device__ float g_att[ACT_ELEMS];
__device__ float g_o[ACT_ELEMS];
__device__ float g_x[ACT_ELEMS];
__device__ __nv_bfloat16 g_xh[ACT_ELEMS];
__device__ __nv_bfloat16 g_xl[ACT_ELEMS];
__device__ __nv_bfloat16 g_ah[ACT_ELEMS];
__device__ __nv_bfloat16 g_al[ACT_ELEMS];
__device__ __nv_bfloat16 g_wh[4 * WELEMS];
__device__ __nv_bfloat16 g_wl[4 * WELEMS];

// ---------------------------------------------------------------------------
// PTX helpers
// ---------------------------------------------------------------------------
__device__ __forceinline__ void ldsm4(unsigned &r0, unsigned &r1, unsigned &r2,
                                      unsigned &r3, unsigned a) {
    asm volatile("ldmatrix.sync.aligned.m8n8.x4.shared.b16 {%0,%1,%2,%3}, [%4];"
                 : "=r"(r0), "=r"(r1), "=r"(r2), "=r"(r3) : "r"(a));
}
__device__ __forceinline__ void mma_bf16(float *c, const unsigned *a,
                                         unsigned b0, unsigned b1) {
    asm volatile(
        "mma.sync.aligned.m16n8k16.row.col.f32.bf16.bf16.f32 "
        "{%0,%1,%2,%3}, {%4,%5,%6,%7}, {%8,%9}, {%0,%1,%2,%3};"
        : "+f"(c[0]), "+f"(c[1]), "+f"(c[2]), "+f"(c[3])
        : "r"(a[0]), "r"(a[1]), "r"(a[2]), "r"(a[3]), "r"(b0), "r"(b1));
}
__device__ __forceinline__ void mma_tf32(float *c, const unsigned *a,
                                         unsigned b0, unsigned b1) {
    asm volatile(
        "mma.sync.aligned.m16n8k8.row.col.f32.tf32.tf32.f32 "
        "{%0,%1,%2,%3}, {%4,%5,%6,%7}, {%8,%9}, {%0,%1,%2,%3};"
        : "+f"(c[0]), "+f"(c[1]), "+f"(c[2]), "+f"(c[3])
        : "r"(a[0]), "r"(a[1]), "r"(a[2]), "r"(a[3]), "r"(b0), "r"(b1));
}
__device__ __forceinline__ void cpa16(unsigned s, const void *g) {
    asm volatile("cp.async.cg.shared.global [%0], [%1], 16;" :: "r"(s), "l"(g));
}
__device__ __forceinline__ void cpcommit() { asm volatile("cp.async.commit_group;"); }
__device__ __forceinline__ void cpwait0() { asm volatile("cp.async.wait_group 0;"); }

// ---------------------------------------------------------------------------
// Split fp32 -> bf16 hi/lo  (vectorized x4)
// ---------------------------------------------------------------------------
__global__ __launch_bounds__(256) void split_kernel(
    const float4 *__restrict__ src, uint2 *__restrict__ hi,
    uint2 *__restrict__ lo, int n4)
{
    int i = blockIdx.x * blockDim.x + threadIdx.x;
    if (i >= n4) return;
    float4 v = src[i];
    __nv_bfloat16 h0 = __float2bfloat16(v.x);
    __nv_bfloat16 h1 = __float2bfloat16(v.y);
    __nv_bfloat16 h2 = __float2bfloat16(v.z);
    __nv_bfloat16 h3 = __float2bfloat16(v.w);
    __nv_bfloat16 l0 = __float2bfloat16(v.x - __bfloat162float(h0));
    __nv_bfloat16 l1 = __float2bfloat16(v.y - __bfloat162float(h1));
    __nv_bfloat16 l2 = __float2bfloat16(v.z - __bfloat162float(h2));
    __nv_bfloat16 l3 = __float2bfloat16(v.w - __bfloat162float(h3));
    uint2 hv, lv;
    hv.x = (unsigned)__bfloat16_as_ushort(h0) | ((unsigned)__bfloat16_as_ushort(h1) << 16);
    hv.y = (unsigned)__bfloat16_as_ushort(h2) | ((unsigned)__bfloat16_as_ushort(h3) << 16);
    lv.x = (unsigned)__bfloat16_as_ushort(l0) | ((unsigned)__bfloat16_as_ushort(l1) << 16);
    lv.y = (unsigned)__bfloat16_as_ushort(l2) | ((unsigned)__bfloat16_as_ushort(l3) << 16);
    hi[i] = hv;
    lo[i] = lv;
}

// ---------------------------------------------------------------------------
// bf16-split GEMM: C[M,N] = (Ah+Al)[M,K] @ (Wh+Wl)[N,K]^T + bias
// Block 128x128, k-chunk 32, 8 warps (warp tile 64x32), cp.async 2-stage.
// Smem rows padded to 80B (stride 5*16B -> conflict-free ldmatrix).
// blockIdx.z selects one of up to 3 (W, bias, C) triples (fused QKV).
// ---------------------------------------------------------------------------
#define TILEB 10240           // 128 rows * 80 B
#define GSTAGE 40960          // 4 tiles per stage
#define GEMM_SMEM (2 * GSTAGE)

__device__ __forceinline__ void gemm_load_stage(
    unsigned sb, int st, int tid,
    const __nv_bfloat16 *Ah, const __nv_bfloat16 *Al,
    const __nv_bfloat16 *Wh, const __nv_bfloat16 *Wl,
    int bm, int bn, int k0)
{
    const int row = tid >> 1;
    const int cb  = (tid & 1) * 2;          // chunk base (0 or 2), 2 chunks each
    unsigned s0 = sb + st * GSTAGE;
    size_t aoff = (size_t)(bm + row) * GK + k0 + cb * 8;
    size_t woff = (size_t)(bn + row) * GK + k0 + cb * 8;
    unsigned sA = s0 + row * 80 + cb * 16;
    cpa16(sA,              Ah + aoff);
    cpa16(sA + 16,         Ah + aoff + 8);
    cpa16(sA + TILEB,      Al + aoff);
    cpa16(sA + TILEB + 16, Al + aoff + 8);
    unsigned sW = s0 + 2 * TILEB + row * 80 + cb * 16;
    cpa16(sW,              Wh + woff);
    cpa16(sW + 16,         Wh + woff + 8);
    cpa16(sW + TILEB,      Wl + woff);
    cpa16(sW + TILEB + 16, Wl + woff + 8);
}

__global__ __launch_bounds__(256, 1) void gemm_split_kernel(
    const __nv_bfloat16 *__restrict__ Ah, const __nv_bfloat16 *__restrict__ Al,
    const __nv_bfloat16 *__restrict__ WhB, const __nv_bfloat16 *__restrict__ WlB,
    const float *__restrict__ b0p, const float *__restrict__ b1p,
    const float *__restrict__ b2p,
    float *__restrict__ c0p, float *__restrict__ c1p, float *__restrict__ c2p)
{
    const int z = blockIdx.z;
    const __nv_bfloat16 *Wh = WhB + (size_t)z * WELEMS;
    const __nv_bfloat16 *Wl = WlB + (size_t)z * WELEMS;
    const float *bias = (z == 0) ? b0p : ((z == 1) ? b1p : b2p);
    float *C          = (z == 0) ? c0p : ((z == 1) ? c1p : c2p);

    extern __shared__ char smc[];
    unsigned sb = (unsigned)__cvta_generic_to_shared(smc);

    const int tid = threadIdx.x;
    const int bm = blockIdx.y * 128, bn = blockIdx.x * 128;
    const int warp = tid >> 5, lane = tid & 31;
    const int wm = (warp >> 2) * 64, wn = (warp & 3) * 32;
    const int gid = lane >> 2, tig = lane & 3;
    const int lrow = lane & 15, lhalf = (lane >> 4) * 16;

    float acc[4][4][4];
#pragma unroll
    for (int mt = 0; mt < 4; mt++)
#pragma unroll
        for (int nt = 0; nt < 4; nt++)
#pragma unroll
            for (int e = 0; e < 4; e++) acc[mt][nt][e] = 0.0f;

    gemm_load_stage(sb, 0, tid, Ah, Al, Wh, Wl, bm, bn, 0);
    cpcommit();

    const int NK = GK / 32;
    for (int ks = 0; ks < NK; ks++) {
        cpwait0();
        __syncthreads();
        if (ks + 1 < NK) {
            gemm_load_stage(sb, (ks + 1) & 1, tid, Ah, Al, Wh, Wl, bm, bn,
                            (ks + 1) * 32);
            cpcommit();
        }
        unsigned s0 = sb + (ks & 1) * GSTAGE;

#pragma unroll
        for (int k16 = 0; k16 < 2; k16++) {
            unsigned ah[4][4], al[4][4], wh[4][2], wl[4][2];
#pragma unroll
            for (int mt = 0; mt < 4; mt++) {
                unsigned addr = s0 + (wm + mt * 16 + lrow) * 80 + k16 * 32 + lhalf;
                ldsm4(ah[mt][0], ah[mt][1], ah[mt][2], ah[mt][3], addr);
                ldsm4(al[mt][0], al[mt][1], al[mt][2], al[mt][3], addr + TILEB);
            }
#pragma unroll
            for (int pr = 0; pr < 2; pr++) {
                unsigned addr = s0 + 2 * TILEB + (wn + pr * 16 + lrow) * 80 +
                                k16 * 32 + lhalf;
                unsigned r0, r1, r2, r3;
                ldsm4(r0, r1, r2, r3, addr);
                wh[2 * pr][0] = r0; wh[2 * pr + 1][0] = r1;
                wh[2 * pr][1] = r2; wh[2 * pr + 1][1] = r3;
                ldsm4(r0, r1, r2, r3, addr + TILEB);
                wl[2 * pr][0] = r0; wl[2 * pr + 1][0] = r1;
                wl[2 * pr][1] = r2; wl[2 * pr + 1][1] = r3;
            }
#pragma unroll
            for (int mt = 0; mt < 4; mt++)
#pragma unroll
                for (int nt = 0; nt < 4; nt++) {
                    mma_bf16(acc[mt][nt], ah[mt], wh[nt][0], wh[nt][1]);
                    mma_bf16(acc[mt][nt], ah[mt], wl[nt][0], wl[nt][1]);
                    mma_bf16(acc[mt][nt], al[mt], wh[nt][0], wh[nt][1]);
                }
        }
        __syncthreads();
    }

    // Epilogue: + bias, store float2 pairs
#pragma unroll
    for (int nt = 0; nt < 4; nt++) {
        int col = bn + wn + nt * 8 + 2 * tig;
        float2 bv = *(const float2 *)(bias + col);
#pragma unroll
        for (int mt = 0; mt < 4; mt++) {
            int r0 = bm + wm + mt * 16 + gid;
            float2 v0 = make_float2(acc[mt][nt][0] + bv.x, acc[mt][nt][1] + bv.y);
            float2 v1 = make_float2(acc[mt][nt][2] + bv.x, acc[mt][nt][3] + bv.y);
            *(float2 *)(C + (size_t)r0 * E_ + col) = v0;
            *(float2 *)(C + (size_t)(r0 + 8) * E_ + col) = v1;
        }
    }
}

// ---------------------------------------------------------------------------
// Flash attention, tf32 mma. Block = 128 q-rows (8 warps x m16), kt tiles of
// 64 keys double-buffered via cp.async. Q frags resident in registers.
// K tile stride 68 floats, V tile stride 72 (each conflict-free for its
// fragment access pattern). P C-layout -> A-layout via warp shfl (no syncs).
// Replicates reference: energy = mask ? -1e-10 : q.k ; softmax(energy/32).
// ---------------------------------------------------------------------------
#define KS_BYTES (64 * 68 * 4)   // 17408
#define VS_BYTES (64 * 72 * 4)   // 18432
#define AST_BYTES (KS_BYTES + VS_BYTES + 256)  // 36096
#define ATT_SMEM (2 * AST_BYTES)

__device__ __forceinline__ void attn_load_stage(
    unsigned sb, int st, int tid,
    const float *K, const float *V, const int *mask,
    size_t hb, int b, int kt)
{
    unsigned s0 = sb + st * AST_BYTES;
    int row = tid >> 2;
    int cb = (tid & 3) * 4;
    const float *kp = K + hb + (size_t)(kt * 64 + row) * E_ + cb * 4;
    const float *vp = V + hb + (size_t)(kt * 64 + row) * E_ + cb * 4;
#pragma unroll
    for (int j = 0; j < 4; j++) {
        cpa16(s0 + row * 272 + (cb + j) * 16, kp + j * 4);
        cpa16(s0 + KS_BYTES + row * 288 + (cb + j) * 16, vp + j * 4);
    }
    if (tid < 16)
        cpa16(s0 + KS_BYTES + VS_BYTES + tid * 16,
              mask + (size_t)b * S_ + kt * 64 + tid * 4);
}

__global__ __launch_bounds__(256, 1) void attn_mma_kernel(
    const float *__restrict__ Q, const float *__restrict__ K,
    const float *__restrict__ V, const int *__restrict__ mask,
    float *__restrict__ O)
{
    extern __shared__ char smc[];
    unsigned sb = (unsigned)__cvta_generic_to_shared(smc);

    const int qt = blockIdx.x, h = blockIdx.y, b = blockIdx.z;
    const int tid = threadIdx.x, warp = tid >> 5, lane = tid & 31;
    const int gid = lane >> 2, tig = lane & 3;
    const size_t hb = (size_t)b * S_ * E_ + (size_t)h * D_;
    const int q0 = qt * 128 + warp * 16;

    // Q fragments (tf32 by bit-reinterpretation of fp32)
    unsigned qf[8][4];
#pragma unroll
    for (int kk = 0; kk < 8; kk++) {
        const float *qp = Q + hb + (size_t)(q0 + gid) * E_ + kk * 8 + tig;
        const float *qp8 = qp + 8 * E_;
        qf[kk][0] = __float_as_uint(qp[0]);
        qf[kk][1] = __float_as_uint(qp8[0]);
        qf[kk][2] = __float_as_uint(qp[4]);
        qf[kk][3] = __float_as_uint(qp8[4]);
    }

    float o[8][4];
#pragma unroll
    for (int nt = 0; nt < 8; nt++)
#pragma unroll
        for (int e = 0; e < 4; e++) o[nt][e] = 0.0f;
    float m0 = -1e30f, m1 = -1e30f, l0 = 0.0f, l1 = 0.0f;

    attn_load_stage(sb, 0, tid, K, V, mask, hb, b, 0);
    cpcommit();

    const float inv_scale = 0.03125f;            // 1/32, exact power of 2
    const float MV = -1e-10f * 0.03125f;         // masked logit
    const unsigned FULL = 0xffffffffu;
    const int srcA = gid * 4 + (tig >> 1);
    const int srcB = srcA + 2;
    const bool odd = (tig & 1) != 0;

    for (int kt = 0; kt < 32; kt++) {
        cpwait0();
        __syncthreads();
        if (kt + 1 < 32) {
            attn_load_stage(sb, (kt + 1) & 1, tid, K, V, mask, hb, b, kt + 1);
            cpcommit();
        }
        const char *stg = smc + (kt & 1) * AST_BYTES;
        const float *Ks = (const float *)stg;
        const float *Vs = (const float *)(stg + KS_BYTES);
        const int *mk = (const int *)(stg + KS_BYTES + VS_BYTES);

        // S = Q @ K^T
        float s[8][4];
#pragma unroll
        for (int nt = 0; nt < 8; nt++) {
            s[nt][0] = s[nt][1] = s[nt][2] = s[nt][3] = 0.0f;
#pragma unroll
            for (int kk = 0; kk < 8; kk++) {
                const float *kfp = Ks + (nt * 8 + gid) * 68 + kk * 8 + tig;
                mma_tf32(s[nt], qf[kk], __float_as_uint(kfp[0]),
                         __float_as_uint(kfp[4]));
            }
        }

        // mask + scale (cols 2tig, 2tig+1 of each n-tile)
#pragma unroll
        for (int nt = 0; nt < 8; nt++) {
            int ms0 = mk[nt * 8 + 2 * tig];
            int ms1 = mk[nt * 8 + 2 * tig + 1];
            s[nt][0] = ms0 ? MV : s[nt][0] * inv_scale;
            s[nt][1] = ms1 ? MV : s[nt][1] * inv_scale;
            s[nt][2] = ms0 ? MV : s[nt][2] * inv_scale;
            s[nt][3] = ms1 ? MV : s[nt][3] * inv_scale;
        }

        // online softmax, rows gid (regs 0,1) and gid+8 (regs 2,3)
        float tm0 = -1e30f, tm1 = -1e30f;
#pragma unroll
        for (int nt = 0; nt < 8; nt++) {
            tm0 = fmaxf(tm0, fmaxf(s[nt][0], s[nt][1]));
            tm1 = fmaxf(tm1, fmaxf(s[nt][2], s[nt][3]));
        }
        tm0 = fmaxf(tm0, __shfl_xor_sync(FULL, tm0, 1));
        tm0 = fmaxf(tm0, __shfl_xor_sync(FULL, tm0, 2));
        tm1 = fmaxf(tm1, __shfl_xor_sync(FULL, tm1, 1));
        tm1 = fmaxf(tm1, __shfl_xor_sync(FULL, tm1, 2));
        float mn0 = fmaxf(m0, tm0), mn1 = fmaxf(m1, tm1);
        float f0 = expf(m0 - mn0), f1 = expf(m1 - mn1);
        float sum0 = 0.0f, sum1 = 0.0f;
#pragma unroll
        for (int nt = 0; nt < 8; nt++) {
            s[nt][0] = expf(s[nt][0] - mn0); sum0 += s[nt][0];
            s[nt][1] = expf(s[nt][1] - mn0); sum0 += s[nt][1];
            s[nt][2] = expf(s[nt][2] - mn1); sum1 += s[nt][2];
            s[nt][3] = expf(s[nt][3] - mn1); sum1 += s[nt][3];
        }
        sum0 += __shfl_xor_sync(FULL, sum0, 1);
        sum0 += __shfl_xor_sync(FULL, sum0, 2);
        sum1 += __shfl_xor_sync(FULL, sum1, 1);
        sum1 += __shfl_xor_sync(FULL, sum1, 2);
        l0 = l0 * f0 + sum0; l1 = l1 * f1 + sum1;
        m0 = mn0; m1 = mn1;
#pragma unroll
        for (int nt = 0; nt < 8; nt++) {
            o[nt][0] *= f0; o[nt][1] *= f0;
            o[nt][2] *= f1; o[nt][3] *= f1;
        }

        // O += P @ V  (P C-layout -> A-frag via shfl)
#pragma unroll
        for (int kk = 0; kk < 8; kk++) {
            unsigned pa[4];
            float v0, v1;
            v0 = __shfl_sync(FULL, s[kk][0], srcA);
            v1 = __shfl_sync(FULL, s[kk][1], srcA);
            pa[0] = __float_as_uint(odd ? v1 : v0);
            v0 = __shfl_sync(FULL, s[kk][2], srcA);
            v1 = __shfl_sync(FULL, s[kk][3], srcA);
            pa[1] = __float_as_uint(odd ? v1 : v0);
            v0 = __shfl_sync(FULL, s[kk][0], srcB);
            v1 = __shfl_sync(FULL, s[kk][1], srcB);
            pa[2] = __float_as_uint(odd ? v1 : v0);
            v0 = __shfl_sync(FULL, s[kk][2], srcB);
            v1 = __shfl_sync(FULL, s[kk][3], srcB);
            pa[3] = __float_as_uint(odd ? v1 : v0);
#pragma unroll
            for (int nt = 0; nt < 8; nt++) {
                const float *vfp = Vs + (kk * 8 + tig) * 72 + nt * 8 + gid;
                mma_tf32(o[nt], pa, __float_as_uint(vfp[0]),
                         __float_as_uint(vfp[4 * 72]));
            }
        }
        __syncthreads();
    }

    // normalize + write
    float i0 = 1.0f / l0, i1 = 1.0f / l1;
#pragma unroll
    for (int nt = 0; nt < 8; nt++) {
        int col = nt * 8 + 2 * tig;
        float2 v0 = make_float2(o[nt][0] * i0, o[nt][1] * i0);
        float2 v1 = make_float2(o[nt][2] * i1, o[nt][3] * i1);
        *(float2 *)(O + hb + (size_t)(q0 + gid) * E_ + col) = v0;
        *(float2 *)(O + hb + (size_t)(q0 + gid + 8) * E_ + col) = v1;
    }
}

// ---------------------------------------------------------------------------
// Residual add + LayerNorm
// ---------------------------------------------------------------------------
__global__ __launch_bounds__(256) void resid_ln_kernel(
    const float *__restrict__ o, const float *__restrict__ x,
    const float *__restrict__ gamma, const float *__restrict__ beta,
    float *__restrict__ out)
{
    const int row = blockIdx.x;
    const int tid = threadIdx.x;
    const float *orow = o + (size_t)row * E_;
    const float *xrow = x + (size_t)row * E_;

    float y[4];
    float s = 0.0f, s2 = 0.0f;
#pragma unroll
    for (int t = 0; t < 4; t++) {
        int c = tid + t * 256;
        y[t] = orow[c] + xrow[c];
        s += y[t];
        s2 += y[t] * y[t];
    }

    __shared__ float red[16];
#pragma unroll
    for (int off = 16; off > 0; off >>= 1) {
        s += __shfl_xor_sync(0xffffffffu, s, off);
        s2 += __shfl_xor_sync(0xffffffffu, s2, off);
    }
    const int warp = tid >> 5, lane = tid & 31;
    if (lane == 0) { red[warp] = s; red[8 + warp] = s2; }
    __syncthreads();

    float ts = 0.0f, ts2 = 0.0f;
#pragma unroll
    for (int w = 0; w < 8; w++) { ts += red[w]; ts2 += red[8 + w]; }

    const float mu = ts * (1.0f / E_);
    const float var = ts2 * (1.0f / E_) - mu * mu;
    const float inv = rsqrtf(var + 1e-5f);

    float *outrow = out + (size_t)row * E_;
#pragma unroll
    for (int t = 0; t < 4; t++) {
        int c = tid + t * 256;
        outrow[c] = (y[t] - mu) * inv * gamma[c] + beta[c];
    }
}

// ---------------------------------------------------------------------------
// Launch
// ---------------------------------------------------------------------------
extern "C" void kernel_launch(void *const *d_in, const int *in_sizes, int n_in,
                              void *d_out, int out_size)
{
    (void)in_sizes; (void)n_in; (void)out_size;

    const float *value = (const float *)d_in[0];
    const int *mask = (const int *)d_in[1];
    const float *Wq = (const float *)d_in[2];  const float *bq = (const float *)d_in[3];
    const float *Wk = (const float *)d_in[4];  const float *bk = (const float *)d_in[5];
    const float *Wv = (const float *)d_in[6];  const float *bv = (const float *)d_in[7];
    const float *Wo = (const float *)d_in[8];  const float *bo = (const float *)d_in[9];
    const float *gamma = (const float *)d_in[10];
    const float *beta = (const float *)d_in[11];
    float *out = (float *)d_out;

    float *q, *k, *v, *att, *o, *x;
    __nv_bfloat16 *xh, *xl, *ah, *al, *wh, *wl;
    cudaGetSymbolAddress((void **)&q, g_q);
    cudaGetSymbolAddress((void **)&k, g_k);
    cudaGetSymbolAddress((void **)&v, g_v);
    cudaGetSymbolAddress((void **)&att, g_att);
    cudaGetSymbolAddress((void **)&o, g_o);
    cudaGetSymbolAddress((void **)&x, g_x);
    cudaGetSymbolAddress((void **)&xh, g_xh);
    cudaGetSymbolAddress((void **)&xl, g_xl);
    cudaGetSymbolAddress((void **)&ah, g_ah);
    cudaGetSymbolAddress((void **)&al, g_al);
    cudaGetSymbolAddress((void **)&wh, g_wh);
    cudaGetSymbolAddress((void **)&wl, g_wl);

    cudaFuncSetAttribute(gemm_split_kernel,
                         cudaFuncAttributeMaxDynamicSharedMemorySize, GEMM_SMEM);
    cudaFuncSetAttribute(attn_mma_kernel,
                         cudaFuncAttributeMaxDynamicSharedMemorySize, ATT_SMEM);

    dim3 qkvgrid(E_ / 128, M_ / 128, 3);
    dim3 ogrid(E_ / 128, M_ / 128, 1);
    dim3 agrid(S_ / 128, H_, B_);
    const int n4a = ACT_ELEMS / 4, n4w = WELEMS / 4;

    const float *xin = value;
    for (int l = 0; l < L_; l++) {
        size_t wof = (size_t)l * WELEMS;
        size_t bof = (size_t)l * E_;

        split_kernel<<<(n4a + 255) / 256, 256>>>((const float4 *)xin,
                                                 (uint2 *)xh, (uint2 *)xl, n4a);
        split_kernel<<<(n4w + 255) / 256, 256>>>((const float4 *)(Wq + wof),
                                                 (uint2 *)wh, (uint2 *)wl, n4w);
        split_kernel<<<(n4w + 255) / 256, 256>>>((const float4 *)(Wk + wof),
                                                 (uint2 *)(wh + WELEMS),
                                                 (uint2 *)(wl + WELEMS), n4w);
        split_kernel<<<(n4w + 255) / 256, 256>>>((const float4 *)(Wv + wof),
                                                 (uint2 *)(wh + 2 * WELEMS),
                                                 (uint2 *)(wl + 2 * WELEMS), n4w);
        split_kernel<<<(n4w + 255) / 256, 256>>>((const float4 *)(Wo + wof),
                                                 (uint2 *)(wh + 3 * WELEMS),
                                                 (uint2 *)(wl + 3 * WELEMS), n4w);

        gemm_split_kernel<<<qkvgrid, 256, GEMM_SMEM>>>(
            xh, xl, wh, wl, bq + bof, bk + bof, bv + bof, q, k, v);

        attn_mma_kernel<<<agrid, 256, ATT_SMEM>>>(q, k, v, mask, att);

        split_kernel<<<(n4a + 255) / 256, 256>>>((const float4 *)att,
                                                 (uint2 *)ah, (uint2 *)al, n4a);

        gemm_split_kernel<<<ogrid, 256, GEMM_SMEM>>>(
            ah, al, wh + 3 * WELEMS, wl + 3 * WELEMS, bo + bof, bo + bof,
            bo + bof, o, o, o);

        float *dst = (l == L_ - 1) ? out : x;
        resid_ln_kernel<<<M_, 256>>>(o, xin, gamma + bof, beta + bof, dst);
        xin = x;
    }
}